// round 2
// baseline (speedup 1.0000x reference)
#include <cuda_runtime.h>
#include <cuda_bf16.h>

// Distral multi-head tiny MLP (N = 32769 heads):
//   h = relu(W1[t] @ x[t] + b1[t]);  logits = W2[t] @ h + b2[t];  out = softmax(logits)
// Layouts (row-major fp32): x(N,3) W1(N,100,3) b1(N,100) W2(N,5,100) b2(N,5) out(N,5)
//
// HBM-bound: ~120MB streamed once. R2 strategy: stage each block's 8 heads via
// contiguous float4 loads into smem (max MLP, LDG.128), compute from smem.

#define HID 100
#define OUT 5
#define HPB 8          // heads per block (1 per warp)
#define THREADS 256

__global__ __launch_bounds__(THREADS) void distral_kernel(
    const float* __restrict__ x,
    const float* __restrict__ W1,
    const float* __restrict__ b1,
    const float* __restrict__ W2,
    const float* __restrict__ b2,
    float* __restrict__ out,
    int n_heads)
{
    __shared__ float s_w1[HPB * HID * 3];   // 2400 floats
    __shared__ float s_b1[HPB * HID];       //  800
    __shared__ float s_w2[HPB * OUT * HID]; // 4000
    __shared__ float s_x [HPB * 3];         //   24
    __shared__ float s_b2[HPB * OUT];       //   40

    const int tid   = threadIdx.x;
    const int head0 = blockIdx.x * HPB;
    const int heads = min(HPB, n_heads - head0);

    // ---- stage: fully coalesced float4 streams (per-block contiguous, 16B aligned:
    //      head0*300/500/100 floats are all multiples of 4 since HPB*... and per-head
    //      counts 300,500,100 are divisible by 4) ----
    {
        const float4* g1 = (const float4*)(W1 + (size_t)head0 * (HID * 3));
        const float4* g2 = (const float4*)(W2 + (size_t)head0 * (OUT * HID));
        const float4* gb = (const float4*)(b1 + (size_t)head0 * HID);
        const int n1 = heads * (HID * 3 / 4);   // 75 per head
        const int n2 = heads * (OUT * HID / 4); // 125 per head
        const int nb = heads * (HID / 4);       // 25 per head

        #pragma unroll 2
        for (int i = tid; i < n2; i += THREADS) ((float4*)s_w2)[i] = g2[i];
        #pragma unroll 2
        for (int i = tid; i < n1; i += THREADS) ((float4*)s_w1)[i] = g1[i];
        for (int i = tid; i < nb; i += THREADS) ((float4*)s_b1)[i] = gb[i];
        // small tails as scalars (not 16B-granular per head count)
        if (tid < heads * 3)   s_x [tid] = x [(size_t)head0 * 3 + tid];
        if (tid < heads * OUT) s_b2[tid] = b2[(size_t)head0 * OUT + tid];
    }
    __syncthreads();

    // ---- compute: one warp per head, all operands in smem ----
    const int w    = tid >> 5;
    const int lane = tid & 31;
    const int head = head0 + w;
    if (head >= n_heads) return;

    const float* w1 = s_w1 + w * (HID * 3);
    const float* w2 = s_w2 + w * (OUT * HID);
    const float* bb = s_b1 + w * HID;
    const float x0 = s_x[w * 3 + 0];
    const float x1 = s_x[w * 3 + 1];
    const float x2 = s_x[w * 3 + 2];

    // hidden: lane covers j = lane + 32m (stride-3 smem: gcd(3,32)=1 -> conflict-free)
    float h[4];
    #pragma unroll
    for (int m = 0; m < 4; m++) {
        int j = lane + 32 * m;
        if (j < HID) {
            float v = fmaf(w1[j * 3 + 0], x0,
                      fmaf(w1[j * 3 + 1], x1,
                      fmaf(w1[j * 3 + 2], x2, bb[j])));
            h[m] = fmaxf(v, 0.0f);
        } else {
            h[m] = 0.0f;
        }
    }

    // logits: stride-1 smem + warp butterfly reduce
    float logits[OUT];
    #pragma unroll
    for (int o = 0; o < OUT; o++) {
        float p = 0.0f;
        #pragma unroll
        for (int m = 0; m < 4; m++) {
            int j = lane + 32 * m;
            if (j < HID) p = fmaf(w2[o * HID + j], h[m], p);
        }
        #pragma unroll
        for (int s = 16; s; s >>= 1)
            p += __shfl_xor_sync(0xffffffffu, p, s);
        logits[o] = p + s_b2[w * OUT + o];
    }

    // softmax over 5 (all lanes hold all logits)
    float mx = logits[0];
    #pragma unroll
    for (int o = 1; o < OUT; o++) mx = fmaxf(mx, logits[o]);
    float e[OUT], sum = 0.0f;
    #pragma unroll
    for (int o = 0; o < OUT; o++) { e[o] = __expf(logits[o] - mx); sum += e[o]; }
    float inv = __frcp_rn(sum);

    if (lane < OUT)
        out[(size_t)head * OUT + lane] = e[lane] * inv;
}

extern "C" void kernel_launch(void* const* d_in, const int* in_sizes, int n_in,
                              void* d_out, int out_size)
{
    const float* x  = (const float*)d_in[0];
    const float* W1 = (const float*)d_in[1];
    const float* b1 = (const float*)d_in[2];
    const float* W2 = (const float*)d_in[3];
    const float* b2 = (const float*)d_in[4];
    float* out = (float*)d_out;

    int n_heads = in_sizes[0] / 3;   // x is (N, 3)
    int blocks = (n_heads + HPB - 1) / HPB;

    distral_kernel<<<blocks, THREADS>>>(x, W1, b1, W2, b2, out, n_heads);
}

// round 3
// speedup vs baseline: 1.3346x; 1.3346x over previous
#include <cuda_runtime.h>
#include <cuda_bf16.h>

// Distral multi-head tiny MLP (N = 32769 heads):
//   h = relu(W1[t] @ x[t] + b1[t]);  logits = W2[t] @ h + b2[t];  out = softmax(logits)
// Layouts (row-major fp32): x(N,3) W1(N,100,3) b1(N,100) W2(N,5,100) b2(N,5) out(N,5)
//
// HBM-bound (~120MB streamed once). R3: one warp per head, but ALL global loads
// are front-batched into registers (MLP_p1 ~ 44) before any compute, with a
// relaxed register budget so ptxas keeps the whole burst in flight. No smem,
// no block barriers (R2 lesson).

#define HID 100
#define OUT 5

__global__ __launch_bounds__(256, 3) void distral_kernel(
    const float* __restrict__ x,
    const float* __restrict__ W1,
    const float* __restrict__ b1,
    const float* __restrict__ W2,
    const float* __restrict__ b2,
    float* __restrict__ out,
    int n_heads)
{
    const int gwarp = (blockIdx.x * blockDim.x + threadIdx.x) >> 5;
    const int lane  = threadIdx.x & 31;
    if (gwarp >= n_heads) return;

    const float* w1  = W1 + (size_t)gwarp * (HID * 3);
    const float* w2  = W2 + (size_t)gwarp * (OUT * HID);
    const float* bb1 = b1 + (size_t)gwarp * HID;
    const float* xg  = x  + (size_t)gwarp * 3;
    const float* bb2 = b2 + (size_t)gwarp * OUT;

    // ================= front-batched load burst (no dependent compute) ==========
    // lane owns hidden units j = lane + 32m, m = 0..3 (j < 100)
    float a2[OUT][4];                       // W2 rows, coalesced stride-1
    #pragma unroll
    for (int o = 0; o < OUT; o++) {
        #pragma unroll
        for (int m = 0; m < 4; m++) {
            int j = lane + 32 * m;
            a2[o][m] = (j < HID) ? w2[o * HID + j] : 0.0f;
        }
    }

    float a1[4][3];                         // W1 rows (stride-3, sector-efficient)
    float ab[4];                            // b1
    #pragma unroll
    for (int m = 0; m < 4; m++) {
        int j = lane + 32 * m;
        bool v = (j < HID);
        a1[m][0] = v ? w1[j * 3 + 0] : 0.0f;
        a1[m][1] = v ? w1[j * 3 + 1] : 0.0f;
        a1[m][2] = v ? w1[j * 3 + 2] : 0.0f;
        ab[m]    = v ? bb1[j]        : 0.0f;
    }

    const float x0 = xg[0], x1 = xg[1], x2 = xg[2];   // warp-broadcast

    float ab2[OUT];                         // b2, warp-broadcast scalars
    #pragma unroll
    for (int o = 0; o < OUT; o++) ab2[o] = bb2[o];

    // ============================ compute ======================================
    float h[4];
    #pragma unroll
    for (int m = 0; m < 4; m++) {
        float v = fmaf(a1[m][0], x0, fmaf(a1[m][1], x1, fmaf(a1[m][2], x2, ab[m])));
        h[m] = fmaxf(v, 0.0f);
    }

    // 5 independent butterfly reductions (interleaved by scheduler)
    float logits[OUT];
    #pragma unroll
    for (int o = 0; o < OUT; o++) {
        float p = fmaf(a2[o][0], h[0],
                  fmaf(a2[o][1], h[1],
                  fmaf(a2[o][2], h[2],
                       a2[o][3] * h[3])));
        #pragma unroll
        for (int s = 16; s; s >>= 1)
            p += __shfl_xor_sync(0xffffffffu, p, s);
        logits[o] = p + ab2[o];
    }

    // softmax over 5 (all lanes redundantly; ALU is free here)
    float mx = logits[0];
    #pragma unroll
    for (int o = 1; o < OUT; o++) mx = fmaxf(mx, logits[o]);
    float e[OUT], sum = 0.0f;
    #pragma unroll
    for (int o = 0; o < OUT; o++) { e[o] = __expf(logits[o] - mx); sum += e[o]; }
    float inv = __frcp_rn(sum);

    if (lane < OUT)
        out[(size_t)gwarp * OUT + lane] = e[lane] * inv;
}

extern "C" void kernel_launch(void* const* d_in, const int* in_sizes, int n_in,
                              void* d_out, int out_size)
{
    const float* x  = (const float*)d_in[0];
    const float* W1 = (const float*)d_in[1];
    const float* b1 = (const float*)d_in[2];
    const float* W2 = (const float*)d_in[3];
    const float* b2 = (const float*)d_in[4];
    float* out = (float*)d_out;

    int n_heads = in_sizes[0] / 3;   // x is (N, 3)
    int warps_per_block = 256 / 32;
    int blocks = (n_heads + warps_per_block - 1) / warps_per_block;

    distral_kernel<<<blocks, 256>>>(x, W1, b1, W2, b2, out, n_heads);
}